// round 12
// baseline (speedup 1.0000x reference)
#include <cuda_runtime.h>
#include <cuda_bf16.h>
#include <math.h>

// Problem constants
static constexpr int cN = 20000;   // nodes
static constexpr int cE = 160000;  // edges
static constexpr int cG = 64;      // graphs

// ---------------------------------------------------------------------------
// Scratch (device globals: allocation-free rule)
// ---------------------------------------------------------------------------
__device__ float g_h[cN * 128];
__device__ float g_q[cN * 1024];
__device__ float g_k[cN * 1024];
__device__ float g_v[cN * 1024];
__device__ float g_r[cN * 128];
__device__ float g_out[cN * 1024];
__device__ float g_logits[cE * 8];
__device__ int   g_deg[cN];
__device__ int   g_rowptr[cN + 1];
__device__ int   g_cursor[cN];
__device__ int   g_perm[cE];
__device__ int   g_srcp[cE];
__device__ float g_bnsum[128];
__device__ float g_bnsq[128];
__device__ float g_pool[cG * 128];
__device__ float g_cnt[cG];

// ---------------------------------------------------------------------------
// CSR build
// ---------------------------------------------------------------------------
__global__ void k_degzero() {
    int i = blockIdx.x * blockDim.x + threadIdx.x;
    if (i < cN) g_deg[i] = 0;
}

__global__ void k_deg(const int* __restrict__ dst) {
    int e = blockIdx.x * blockDim.x + threadIdx.x;
    if (e < cE) atomicAdd(&g_deg[dst[e]], 1);
}

// single-block exclusive scan over g_deg -> g_rowptr, g_cursor
__global__ void k_scan() {
    __shared__ int warpsum[32];
    __shared__ int s_carry;
    int tid = threadIdx.x;              // 1024 threads
    int lane = tid & 31, w = tid >> 5;
    if (tid == 0) s_carry = 0;
    __syncthreads();
    for (int base = 0; base < cN; base += 1024) {
        int i = base + tid;
        int v = (i < cN) ? g_deg[i] : 0;
        int x = v;
        #pragma unroll
        for (int o = 1; o < 32; o <<= 1) {
            int y = __shfl_up_sync(0xffffffffu, x, o);
            if (lane >= o) x += y;
        }
        if (lane == 31) warpsum[w] = x;
        __syncthreads();
        if (w == 0) {
            int y = warpsum[lane];
            #pragma unroll
            for (int o = 1; o < 32; o <<= 1) {
                int z = __shfl_up_sync(0xffffffffu, y, o);
                if (lane >= o) y += z;
            }
            warpsum[lane] = y;
        }
        __syncthreads();
        int incl = x + (w > 0 ? warpsum[w - 1] : 0) + s_carry;
        int excl = incl - v;
        if (i < cN) { g_rowptr[i] = excl; g_cursor[i] = excl; }
        if (i == cN - 1) g_rowptr[cN] = incl;
        __syncthreads();
        if (tid == 1023) s_carry = incl;
        __syncthreads();
    }
}

__global__ void k_scatter(const int* __restrict__ src, const int* __restrict__ dst) {
    int e = blockIdx.x * blockDim.x + threadIdx.x;
    if (e < cE) {
        int d = dst[e];
        int pos = atomicAdd(&g_cursor[d], 1);
        g_perm[pos] = e;
        g_srcp[pos] = src[e];
    }
}

// ---------------------------------------------------------------------------
// GEMM:  C[cN, M] = A[cN, 128] @ W[128, M] + bias   (M in {128, 1024})
// BM=64 BN=64 BK=16, 256 threads, 4x4 per thread
// ---------------------------------------------------------------------------
__global__ void k_gemm(const float* __restrict__ A, const float* __restrict__ W,
                       const float* __restrict__ bias, float* __restrict__ C, int M) {
    __shared__ float As[16][64];
    __shared__ float Bs[16][64];
    const int bm = blockIdx.x * 64, bn = blockIdx.y * 64;
    const int tid = threadIdx.x;
    const int tx = tid & 15, ty = tid >> 4;

    float acc[4][4];
    #pragma unroll
    for (int i = 0; i < 4; i++)
        #pragma unroll
        for (int j = 0; j < 4; j++) acc[i][j] = 0.f;

    for (int k0 = 0; k0 < 128; k0 += 16) {
        #pragma unroll
        for (int t = tid; t < 1024; t += 256) {
            int r = t >> 4, c = t & 15;
            int row = bm + r;
            As[c][r] = (row < cN) ? A[(size_t)row * 128 + k0 + c] : 0.f;
        }
        #pragma unroll
        for (int t = tid; t < 1024; t += 256) {
            int r = t >> 6, c = t & 63;
            Bs[r][c] = W[(size_t)(k0 + r) * M + bn + c];
        }
        __syncthreads();
        #pragma unroll
        for (int kk = 0; kk < 16; kk++) {
            float4 a = *(const float4*)&As[kk][ty * 4];
            float4 b = *(const float4*)&Bs[kk][tx * 4];
            float av[4] = {a.x, a.y, a.z, a.w};
            float bv[4] = {b.x, b.y, b.z, b.w};
            #pragma unroll
            for (int i = 0; i < 4; i++)
                #pragma unroll
                for (int j = 0; j < 4; j++) acc[i][j] += av[i] * bv[j];
        }
        __syncthreads();
    }
    #pragma unroll
    for (int i = 0; i < 4; i++) {
        int row = bm + ty * 4 + i;
        if (row < cN) {
            #pragma unroll
            for (int j = 0; j < 4; j++) {
                int col = bn + tx * 4 + j;
                C[(size_t)row * M + col] = acc[i][j] + bias[col];
            }
        }
    }
}

// ---------------------------------------------------------------------------
// Edge attention logits: logits[e,h] = dot(q[dst,h,:], k[src,h,:]) * scale
// ---------------------------------------------------------------------------
__global__ void k_logits(const int* __restrict__ src, const int* __restrict__ dst,
                         int d, float scale) {
    int idx = blockIdx.x * blockDim.x + threadIdx.x;
    if (idx >= cE * 8) return;
    int e = idx >> 3, h = idx & 7;
    int s = src[e], t = dst[e];
    const float4* qp = (const float4*)(g_q + (size_t)t * (8 * d) + h * d);
    const float4* kp = (const float4*)(g_k + (size_t)s * (8 * d) + h * d);
    float a0 = 0.f, a1 = 0.f;
    int n4 = d >> 2;
    #pragma unroll 4
    for (int j = 0; j < n4; j += 2) {
        float4 a = qp[j],     b = kp[j];
        float4 c = qp[j + 1], dd = kp[j + 1];
        a0 += a.x * b.x + a.y * b.y + a.z * b.z + a.w * b.w;
        a1 += c.x * dd.x + c.y * dd.y + c.z * dd.z + c.w * dd.w;
    }
    g_logits[idx] = (a0 + a1) * scale;
}

// ---------------------------------------------------------------------------
// Segment softmax + aggregation, d=16 (layers 0..2): one warp per node.
// Lane owns head h=lane&7 for stats; float4 of out components for accumulation.
// ---------------------------------------------------------------------------
__global__ void k_attn16() {
    int n = blockIdx.x * 8 + (threadIdx.x >> 5);
    if (n >= cN) return;
    int lane = threadIdx.x & 31;
    int beg = g_rowptr[n], end = g_rowptr[n + 1];
    int h = lane & 7;
    float mx = -1e30f;
    for (int i = beg + (lane >> 3); i < end; i += 4)
        mx = fmaxf(mx, g_logits[g_perm[i] * 8 + h]);
    mx = fmaxf(mx, __shfl_xor_sync(0xffffffffu, mx, 8));
    mx = fmaxf(mx, __shfl_xor_sync(0xffffffffu, mx, 16));
    float den = 0.f;
    for (int i = beg + (lane >> 3); i < end; i += 4)
        den += __expf(g_logits[g_perm[i] * 8 + h] - mx);
    den += __shfl_xor_sync(0xffffffffu, den, 8);
    den += __shfl_xor_sync(0xffffffffu, den, 16);
    // lane's output float4 covers components [4*lane, 4*lane+4) -> head = lane>>2
    int hh = lane >> 2;
    float m2 = __shfl_sync(0xffffffffu, mx, hh);
    float d2 = __shfl_sync(0xffffffffu, den, hh);
    float rden = 1.f / (d2 + 1e-16f);
    float4 acc = {0.f, 0.f, 0.f, 0.f};
    for (int i = beg; i < end; i++) {
        float w = __expf(g_logits[g_perm[i] * 8 + hh] - m2) * rden;
        const float4 vv = *(const float4*)(g_v + (size_t)g_srcp[i] * 128 + lane * 4);
        acc.x += w * vv.x; acc.y += w * vv.y; acc.z += w * vv.z; acc.w += w * vv.w;
    }
    *(float4*)(g_out + (size_t)n * 128 + lane * 4) = acc;
}

// d=128 (layer 3): one warp per (node, head)
__global__ void k_attn128() {
    int wid = blockIdx.x * 8 + (threadIdx.x >> 5);
    if (wid >= cN * 8) return;
    int n = wid >> 3, h = wid & 7;
    int lane = threadIdx.x & 31;
    int beg = g_rowptr[n], end = g_rowptr[n + 1];
    float mx = -1e30f;
    for (int i = beg + lane; i < end; i += 32)
        mx = fmaxf(mx, g_logits[g_perm[i] * 8 + h]);
    #pragma unroll
    for (int o = 16; o; o >>= 1) mx = fmaxf(mx, __shfl_xor_sync(0xffffffffu, mx, o));
    float den = 0.f;
    for (int i = beg + lane; i < end; i += 32)
        den += __expf(g_logits[g_perm[i] * 8 + h] - mx);
    #pragma unroll
    for (int o = 16; o; o >>= 1) den += __shfl_xor_sync(0xffffffffu, den, o);
    float rden = 1.f / (den + 1e-16f);
    float4 acc = {0.f, 0.f, 0.f, 0.f};
    for (int i = beg; i < end; i++) {
        float w = __expf(g_logits[g_perm[i] * 8 + h] - mx) * rden;
        const float4 vv = *(const float4*)(g_v + (size_t)g_srcp[i] * 1024 + h * 128 + lane * 4);
        acc.x += w * vv.x; acc.y += w * vv.y; acc.z += w * vv.z; acc.w += w * vv.w;
    }
    *(float4*)(g_out + (size_t)n * 1024 + h * 128 + lane * 4) = acc;
}

// ---------------------------------------------------------------------------
// Beta-gated skip: g = sigmoid([out, r, out-r] @ Wb); h = g*r + (1-g)*out
// One warp per node.
// ---------------------------------------------------------------------------
__device__ __forceinline__ void beta_core(int n, int lane, float4 o, const float* Wb) {
    float4 r  = *(const float4*)&g_r[(size_t)n * 128 + lane * 4];
    float4 w0 = *(const float4*)&Wb[lane * 4];
    float4 w1 = *(const float4*)&Wb[128 + lane * 4];
    float4 w2 = *(const float4*)&Wb[256 + lane * 4];
    float s = o.x * (w0.x + w2.x) + r.x * (w1.x - w2.x)
            + o.y * (w0.y + w2.y) + r.y * (w1.y - w2.y)
            + o.z * (w0.z + w2.z) + r.z * (w1.z - w2.z)
            + o.w * (w0.w + w2.w) + r.w * (w1.w - w2.w);
    #pragma unroll
    for (int off = 16; off; off >>= 1) s += __shfl_xor_sync(0xffffffffu, s, off);
    float g = 1.f / (1.f + __expf(-s));
    float4 res;
    res.x = g * r.x + (1.f - g) * o.x;
    res.y = g * r.y + (1.f - g) * o.y;
    res.z = g * r.z + (1.f - g) * o.z;
    res.w = g * r.w + (1.f - g) * o.w;
    *(float4*)&g_h[(size_t)n * 128 + lane * 4] = res;
}

__global__ void k_beta(const float* __restrict__ Wb) {
    int n = blockIdx.x * 8 + (threadIdx.x >> 5);
    if (n >= cN) return;
    int lane = threadIdx.x & 31;
    float4 o = *(const float4*)&g_out[(size_t)n * 128 + lane * 4];
    beta_core(n, lane, o, Wb);
}

// layer 3: out = mean over heads of g_out[n, head, :]
__global__ void k_beta3(const float* __restrict__ Wb) {
    int n = blockIdx.x * 8 + (threadIdx.x >> 5);
    if (n >= cN) return;
    int lane = threadIdx.x & 31;
    float4 o = {0.f, 0.f, 0.f, 0.f};
    #pragma unroll
    for (int hh = 0; hh < 8; hh++) {
        float4 t = *(const float4*)&g_out[(size_t)n * 1024 + hh * 128 + lane * 4];
        o.x += t.x; o.y += t.y; o.z += t.z; o.w += t.w;
    }
    o.x *= 0.125f; o.y *= 0.125f; o.z *= 0.125f; o.w *= 0.125f;
    beta_core(n, lane, o, Wb);
}

// ---------------------------------------------------------------------------
// BatchNorm over nodes (per column), fused ReLU in apply
// ---------------------------------------------------------------------------
__global__ void k_bnzero() {
    int i = threadIdx.x;
    if (i < 128) { g_bnsum[i] = 0.f; g_bnsq[i] = 0.f; }
}

__global__ void k_bnstat() {
    int c = threadIdx.x;  // 128 threads
    float s = 0.f, sq = 0.f;
    for (int row = blockIdx.x; row < cN; row += gridDim.x) {
        float x = g_h[(size_t)row * 128 + c];
        s += x; sq += x * x;
    }
    atomicAdd(&g_bnsum[c], s);
    atomicAdd(&g_bnsq[c], sq);
}

__global__ void k_bnapply(const float* __restrict__ gamma, const float* __restrict__ beta) {
    int idx = blockIdx.x * blockDim.x + threadIdx.x;
    if (idx >= cN * 128) return;
    int c = idx & 127;
    float mu = g_bnsum[c] * (1.f / cN);
    float var = g_bnsq[c] * (1.f / cN) - mu * mu;
    float x = (g_h[idx] - mu) * rsqrtf(var + 1e-5f) * gamma[c] + beta[c];
    g_h[idx] = fmaxf(x, 0.f);
}

// ---------------------------------------------------------------------------
// Global mean pool per graph
// ---------------------------------------------------------------------------
__global__ void k_poolzero() {
    int i = blockIdx.x * blockDim.x + threadIdx.x;
    if (i < cG * 128) g_pool[i] = 0.f;
    if (i < cG) g_cnt[i] = 0.f;
}

__global__ void k_pool(const int* __restrict__ batch) {
    int idx = blockIdx.x * blockDim.x + threadIdx.x;
    if (idx >= cN * 128) return;
    int n = idx >> 7, c = idx & 127;
    int b = batch[n];
    atomicAdd(&g_pool[b * 128 + c], g_h[idx]);
    if (c == 0) atomicAdd(&g_cnt[b], 1.f);
}

__global__ void k_poolout(float* __restrict__ out) {
    int idx = blockIdx.x * blockDim.x + threadIdx.x;
    if (idx >= cG * 128) return;
    int b = idx >> 7;
    out[idx] = g_pool[idx] / fmaxf(g_cnt[b], 1.f);
}

// ---------------------------------------------------------------------------
// Launch
// ---------------------------------------------------------------------------
extern "C" void kernel_launch(void* const* d_in, const int* in_sizes, int n_in,
                              void* d_out, int out_size) {
    const float* x   = (const float*)d_in[0];
    const int*   ei  = (const int*)d_in[1];
    const int*   bat = (const int*)d_in[2];
    const float* Wp  = (const float*)d_in[3];
    const float* bp  = (const float*)d_in[4];
    const float* Wq  = (const float*)d_in[5];
    const float* bq  = (const float*)d_in[6];
    const float* Wk  = (const float*)d_in[7];
    const float* bk  = (const float*)d_in[8];
    const float* Wv  = (const float*)d_in[9];
    const float* bv  = (const float*)d_in[10];
    const float* Ws  = (const float*)d_in[11];
    const float* bs  = (const float*)d_in[12];
    const float* Wb  = (const float*)d_in[13];
    const float* Wq3 = (const float*)d_in[14];
    const float* bq3 = (const float*)d_in[15];
    const float* Wk3 = (const float*)d_in[16];
    const float* bk3 = (const float*)d_in[17];
    const float* Wv3 = (const float*)d_in[18];
    const float* bv3 = (const float*)d_in[19];
    const float* Ws3 = (const float*)d_in[20];
    const float* bs3 = (const float*)d_in[21];
    const float* Wb3 = (const float*)d_in[22];
    const float* bng = (const float*)d_in[23];
    const float* bnb = (const float*)d_in[24];
    float* out = (float*)d_out;
    const int* src = ei;
    const int* dst = ei + cE;

    float *p_h, *p_q, *p_k, *p_v, *p_r;
    cudaGetSymbolAddress((void**)&p_h, g_h);
    cudaGetSymbolAddress((void**)&p_q, g_q);
    cudaGetSymbolAddress((void**)&p_k, g_k);
    cudaGetSymbolAddress((void**)&p_v, g_v);
    cudaGetSymbolAddress((void**)&p_r, g_r);

    const int nodeWarps = (cN + 7) / 8;       // 8 warps / 256-thread block
    const int elemBlks  = (cN * 128 + 255) / 256;
    dim3 g128((cN + 63) / 64, 2);
    dim3 g1024((cN + 63) / 64, 16);

    // CSR build (graph fixed, rebuilt each launch for determinism-of-work)
    k_degzero<<<(cN + 255) / 256, 256>>>();
    k_deg<<<(cE + 255) / 256, 256>>>(dst);
    k_scan<<<1, 1024>>>();
    k_scatter<<<(cE + 255) / 256, 256>>>(src, dst);

    // initial projection
    k_gemm<<<g128, 256>>>(x, Wp, bp, p_h, 128);

    // layers 0..2 (heads=8, d=16, concat)
    for (int i = 0; i < 3; i++) {
        k_gemm<<<g128, 256>>>(p_h, Wq + i * 16384, bq + i * 128, p_q, 128);
        k_gemm<<<g128, 256>>>(p_h, Wk + i * 16384, bk + i * 128, p_k, 128);
        k_gemm<<<g128, 256>>>(p_h, Wv + i * 16384, bv + i * 128, p_v, 128);
        k_gemm<<<g128, 256>>>(p_h, Ws + i * 16384, bs + i * 128, p_r, 128);
        k_logits<<<(cE * 8 + 255) / 256, 256>>>(src, dst, 16, 0.25f);
        k_attn16<<<nodeWarps, 256>>>();
        k_beta<<<nodeWarps, 256>>>(Wb + i * 384);
        k_bnzero<<<1, 128>>>();
        k_bnstat<<<256, 128>>>();
        k_bnapply<<<elemBlks, 256>>>(bng + i * 128, bnb + i * 128);
    }

    // layer 3 (heads=8, d=128, head-mean)
    k_gemm<<<g1024, 256>>>(p_h, Wq3, bq3, p_q, 1024);
    k_gemm<<<g1024, 256>>>(p_h, Wk3, bk3, p_k, 1024);
    k_gemm<<<g1024, 256>>>(p_h, Wv3, bv3, p_v, 1024);
    k_gemm<<<g128, 256>>>(p_h, Ws3, bs3, p_r, 128);
    k_logits<<<(cE * 8 + 255) / 256, 256>>>(src, dst, 128, 0.08838834764831845f);
    k_attn128<<<(cN * 8 + 7) / 8, 256>>>();
    k_beta3<<<nodeWarps, 256>>>(Wb3);
    k_bnzero<<<1, 128>>>();
    k_bnstat<<<256, 128>>>();
    k_bnapply<<<elemBlks, 256>>>(bng + 3 * 128, bnb + 3 * 128);

    // global mean pool
    k_poolzero<<<32, 256>>>();
    k_pool<<<elemBlks, 256>>>(bat);
    k_poolout<<<32, 256>>>(out);
}

// round 13
// speedup vs baseline: 1.0453x; 1.0453x over previous
#include <cuda_runtime.h>
#include <cuda_bf16.h>
#include <math.h>

// Problem constants
static constexpr int cN = 20000;   // nodes
static constexpr int cE = 160000;  // edges
static constexpr int cG = 64;      // graphs

// ---------------------------------------------------------------------------
// Scratch (device globals: allocation-free rule)
// ---------------------------------------------------------------------------
__device__ float g_h[cN * 128];
__device__ float g_q[cN * 1024];
__device__ float g_k[cN * 1024];
__device__ float g_v[cN * 1024];
__device__ float g_r[cN * 128];
__device__ float g_out[cN * 1024];
__device__ float g_logits[cE * 8];
__device__ int   g_deg[cN];
__device__ int   g_rowptr[cN + 1];
__device__ int   g_cursor[cN];
__device__ int   g_perm[cE];
__device__ int   g_srcp[cE];
__device__ float g_bnsum[128];
__device__ float g_bnsq[128];
__device__ float g_pool[cG * 128];
__device__ float g_cnt[cG];

// ---------------------------------------------------------------------------
// CSR build
// ---------------------------------------------------------------------------
__global__ void k_degzero() {
    int i = blockIdx.x * blockDim.x + threadIdx.x;
    if (i < cN) g_deg[i] = 0;
}

__global__ void k_deg(const int* __restrict__ dst) {
    int e = blockIdx.x * blockDim.x + threadIdx.x;
    if (e < cE) atomicAdd(&g_deg[dst[e]], 1);
}

// single-block exclusive scan over g_deg -> g_rowptr, g_cursor
__global__ void k_scan() {
    __shared__ int warpsum[32];
    __shared__ int s_carry;
    int tid = threadIdx.x;              // 1024 threads
    int lane = tid & 31, w = tid >> 5;
    if (tid == 0) s_carry = 0;
    __syncthreads();
    for (int base = 0; base < cN; base += 1024) {
        int i = base + tid;
        int v = (i < cN) ? g_deg[i] : 0;
        int x = v;
        #pragma unroll
        for (int o = 1; o < 32; o <<= 1) {
            int y = __shfl_up_sync(0xffffffffu, x, o);
            if (lane >= o) x += y;
        }
        if (lane == 31) warpsum[w] = x;
        __syncthreads();
        if (w == 0) {
            int y = warpsum[lane];
            #pragma unroll
            for (int o = 1; o < 32; o <<= 1) {
                int z = __shfl_up_sync(0xffffffffu, y, o);
                if (lane >= o) y += z;
            }
            warpsum[lane] = y;
        }
        __syncthreads();
        int incl = x + (w > 0 ? warpsum[w - 1] : 0) + s_carry;
        int excl = incl - v;
        if (i < cN) { g_rowptr[i] = excl; g_cursor[i] = excl; }
        if (i == cN - 1) g_rowptr[cN] = incl;
        __syncthreads();
        if (tid == 1023) s_carry = incl;
        __syncthreads();
    }
}

__global__ void k_scatter(const int* __restrict__ src, const int* __restrict__ dst) {
    int e = blockIdx.x * blockDim.x + threadIdx.x;
    if (e < cE) {
        int d = dst[e];
        int pos = atomicAdd(&g_cursor[d], 1);
        g_perm[pos] = e;
        g_srcp[pos] = src[e];
    }
}

// ---------------------------------------------------------------------------
// GEMM:  C[cN, M] = A[cN, 128] @ W[128, M] + bias   (M in {128, 1024})
// BM=64 BN=64 BK=16, 256 threads, 4x4 per thread
// ---------------------------------------------------------------------------
__global__ void k_gemm(const float* __restrict__ A, const float* __restrict__ W,
                       const float* __restrict__ bias, float* __restrict__ C, int M) {
    __shared__ float As[16][64];
    __shared__ float Bs[16][64];
    const int bm = blockIdx.x * 64, bn = blockIdx.y * 64;
    const int tid = threadIdx.x;
    const int tx = tid & 15, ty = tid >> 4;

    float acc[4][4];
    #pragma unroll
    for (int i = 0; i < 4; i++)
        #pragma unroll
        for (int j = 0; j < 4; j++) acc[i][j] = 0.f;

    for (int k0 = 0; k0 < 128; k0 += 16) {
        #pragma unroll
        for (int t = tid; t < 1024; t += 256) {
            int r = t >> 4, c = t & 15;
            int row = bm + r;
            As[c][r] = (row < cN) ? A[(size_t)row * 128 + k0 + c] : 0.f;
        }
        #pragma unroll
        for (int t = tid; t < 1024; t += 256) {
            int r = t >> 6, c = t & 63;
            Bs[r][c] = W[(size_t)(k0 + r) * M + bn + c];
        }
        __syncthreads();
        #pragma unroll
        for (int kk = 0; kk < 16; kk++) {
            float4 a = *(const float4*)&As[kk][ty * 4];
            float4 b = *(const float4*)&Bs[kk][tx * 4];
            float av[4] = {a.x, a.y, a.z, a.w};
            float bv[4] = {b.x, b.y, b.z, b.w};
            #pragma unroll
            for (int i = 0; i < 4; i++)
                #pragma unroll
                for (int j = 0; j < 4; j++) acc[i][j] += av[i] * bv[j];
        }
        __syncthreads();
    }
    #pragma unroll
    for (int i = 0; i < 4; i++) {
        int row = bm + ty * 4 + i;
        if (row < cN) {
            #pragma unroll
            for (int j = 0; j < 4; j++) {
                int col = bn + tx * 4 + j;
                C[(size_t)row * M + col] = acc[i][j] + bias[col];
            }
        }
    }
}

// ---------------------------------------------------------------------------
// Edge attention logits: logits[e,h] = dot(q[dst,h,:], k[src,h,:]) * scale
// ---------------------------------------------------------------------------
__global__ void k_logits(const int* __restrict__ src, const int* __restrict__ dst,
                         int d, float scale) {
    int idx = blockIdx.x * blockDim.x + threadIdx.x;
    if (idx >= cE * 8) return;
    int e = idx >> 3, h = idx & 7;
    int s = src[e], t = dst[e];
    const float4* qp = (const float4*)(g_q + (size_t)t * (8 * d) + h * d);
    const float4* kp = (const float4*)(g_k + (size_t)s * (8 * d) + h * d);
    float a0 = 0.f, a1 = 0.f;
    int n4 = d >> 2;
    #pragma unroll 4
    for (int j = 0; j < n4; j += 2) {
        float4 a = qp[j],     b = kp[j];
        float4 c = qp[j + 1], dd = kp[j + 1];
        a0 += a.x * b.x + a.y * b.y + a.z * b.z + a.w * b.w;
        a1 += c.x * dd.x + c.y * dd.y + c.z * dd.z + c.w * dd.w;
    }
    g_logits[idx] = (a0 + a1) * scale;
}

// ---------------------------------------------------------------------------
// Segment softmax + aggregation, d=16 (layers 0..2): one warp per node.
// Lane owns head h=lane&7 for stats; float4 of out components for accumulation.
// ---------------------------------------------------------------------------
__global__ void k_attn16() {
    int n = blockIdx.x * 8 + (threadIdx.x >> 5);
    if (n >= cN) return;
    int lane = threadIdx.x & 31;
    int beg = g_rowptr[n], end = g_rowptr[n + 1];
    int h = lane & 7;
    float mx = -1e30f;
    for (int i = beg + (lane >> 3); i < end; i += 4)
        mx = fmaxf(mx, g_logits[g_perm[i] * 8 + h]);
    mx = fmaxf(mx, __shfl_xor_sync(0xffffffffu, mx, 8));
    mx = fmaxf(mx, __shfl_xor_sync(0xffffffffu, mx, 16));
    float den = 0.f;
    for (int i = beg + (lane >> 3); i < end; i += 4)
        den += __expf(g_logits[g_perm[i] * 8 + h] - mx);
    den += __shfl_xor_sync(0xffffffffu, den, 8);
    den += __shfl_xor_sync(0xffffffffu, den, 16);
    // lane's output float4 covers components [4*lane, 4*lane+4) -> head = lane>>2
    int hh = lane >> 2;
    float m2 = __shfl_sync(0xffffffffu, mx, hh);
    float d2 = __shfl_sync(0xffffffffu, den, hh);
    float rden = 1.f / (d2 + 1e-16f);
    float4 acc = {0.f, 0.f, 0.f, 0.f};
    for (int i = beg; i < end; i++) {
        float w = __expf(g_logits[g_perm[i] * 8 + hh] - m2) * rden;
        const float4 vv = *(const float4*)(g_v + (size_t)g_srcp[i] * 128 + lane * 4);
        acc.x += w * vv.x; acc.y += w * vv.y; acc.z += w * vv.z; acc.w += w * vv.w;
    }
    *(float4*)(g_out + (size_t)n * 128 + lane * 4) = acc;
}

// d=128 (layer 3): one warp per (node, head)
__global__ void k_attn128() {
    int wid = blockIdx.x * 8 + (threadIdx.x >> 5);
    if (wid >= cN * 8) return;
    int n = wid >> 3, h = wid & 7;
    int lane = threadIdx.x & 31;
    int beg = g_rowptr[n], end = g_rowptr[n + 1];
    float mx = -1e30f;
    for (int i = beg + lane; i < end; i += 32)
        mx = fmaxf(mx, g_logits[g_perm[i] * 8 + h]);
    #pragma unroll
    for (int o = 16; o; o >>= 1) mx = fmaxf(mx, __shfl_xor_sync(0xffffffffu, mx, o));
    float den = 0.f;
    for (int i = beg + lane; i < end; i += 32)
        den += __expf(g_logits[g_perm[i] * 8 + h] - mx);
    #pragma unroll
    for (int o = 16; o; o >>= 1) den += __shfl_xor_sync(0xffffffffu, den, o);
    float rden = 1.f / (den + 1e-16f);
    float4 acc = {0.f, 0.f, 0.f, 0.f};
    for (int i = beg; i < end; i++) {
        float w = __expf(g_logits[g_perm[i] * 8 + h] - mx) * rden;
        const float4 vv = *(const float4*)(g_v + (size_t)g_srcp[i] * 1024 + h * 128 + lane * 4);
        acc.x += w * vv.x; acc.y += w * vv.y; acc.z += w * vv.z; acc.w += w * vv.w;
    }
    *(float4*)(g_out + (size_t)n * 1024 + h * 128 + lane * 4) = acc;
}

// ---------------------------------------------------------------------------
// Beta-gated skip: g = sigmoid([out, r, out-r] @ Wb); h = g*r + (1-g)*out
// One warp per node.
// ---------------------------------------------------------------------------
__device__ __forceinline__ void beta_core(int n, int lane, float4 o, const float* Wb) {
    float4 r  = *(const float4*)&g_r[(size_t)n * 128 + lane * 4];
    float4 w0 = *(const float4*)&Wb[lane * 4];
    float4 w1 = *(const float4*)&Wb[128 + lane * 4];
    float4 w2 = *(const float4*)&Wb[256 + lane * 4];
    float s = o.x * (w0.x + w2.x) + r.x * (w1.x - w2.x)
            + o.y * (w0.y + w2.y) + r.y * (w1.y - w2.y)
            + o.z * (w0.z + w2.z) + r.z * (w1.z - w2.z)
            + o.w * (w0.w + w2.w) + r.w * (w1.w - w2.w);
    #pragma unroll
    for (int off = 16; off; off >>= 1) s += __shfl_xor_sync(0xffffffffu, s, off);
    float g = 1.f / (1.f + __expf(-s));
    float4 res;
    res.x = g * r.x + (1.f - g) * o.x;
    res.y = g * r.y + (1.f - g) * o.y;
    res.z = g * r.z + (1.f - g) * o.z;
    res.w = g * r.w + (1.f - g) * o.w;
    *(float4*)&g_h[(size_t)n * 128 + lane * 4] = res;
}

__global__ void k_beta(const float* __restrict__ Wb) {
    int n = blockIdx.x * 8 + (threadIdx.x >> 5);
    if (n >= cN) return;
    int lane = threadIdx.x & 31;
    float4 o = *(const float4*)&g_out[(size_t)n * 128 + lane * 4];
    beta_core(n, lane, o, Wb);
}

// layer 3: out = mean over heads of g_out[n, head, :]
__global__ void k_beta3(const float* __restrict__ Wb) {
    int n = blockIdx.x * 8 + (threadIdx.x >> 5);
    if (n >= cN) return;
    int lane = threadIdx.x & 31;
    float4 o = {0.f, 0.f, 0.f, 0.f};
    #pragma unroll
    for (int hh = 0; hh < 8; hh++) {
        float4 t = *(const float4*)&g_out[(size_t)n * 1024 + hh * 128 + lane * 4];
        o.x += t.x; o.y += t.y; o.z += t.z; o.w += t.w;
    }
    o.x *= 0.125f; o.y *= 0.125f; o.z *= 0.125f; o.w *= 0.125f;
    beta_core(n, lane, o, Wb);
}

// ---------------------------------------------------------------------------
// BatchNorm over nodes (per column), fused ReLU in apply
// ---------------------------------------------------------------------------
__global__ void k_bnzero() {
    int i = threadIdx.x;
    if (i < 128) { g_bnsum[i] = 0.f; g_bnsq[i] = 0.f; }
}

__global__ void k_bnstat() {
    int c = threadIdx.x;  // 128 threads
    float s = 0.f, sq = 0.f;
    for (int row = blockIdx.x; row < cN; row += gridDim.x) {
        float x = g_h[(size_t)row * 128 + c];
        s += x; sq += x * x;
    }
    atomicAdd(&g_bnsum[c], s);
    atomicAdd(&g_bnsq[c], sq);
}

__global__ void k_bnapply(const float* __restrict__ gamma, const float* __restrict__ beta) {
    int idx = blockIdx.x * blockDim.x + threadIdx.x;
    if (idx >= cN * 128) return;
    int c = idx & 127;
    float mu = g_bnsum[c] * (1.f / cN);
    float var = g_bnsq[c] * (1.f / cN) - mu * mu;
    float x = (g_h[idx] - mu) * rsqrtf(var + 1e-5f) * gamma[c] + beta[c];
    g_h[idx] = fmaxf(x, 0.f);
}

// ---------------------------------------------------------------------------
// Global mean pool per graph
// ---------------------------------------------------------------------------
__global__ void k_poolzero() {
    int i = blockIdx.x * blockDim.x + threadIdx.x;
    if (i < cG * 128) g_pool[i] = 0.f;
    if (i < cG) g_cnt[i] = 0.f;
}

__global__ void k_pool(const int* __restrict__ batch) {
    int idx = blockIdx.x * blockDim.x + threadIdx.x;
    if (idx >= cN * 128) return;
    int n = idx >> 7, c = idx & 127;
    int b = batch[n];
    atomicAdd(&g_pool[b * 128 + c], g_h[idx]);
    if (c == 0) atomicAdd(&g_cnt[b], 1.f);
}

__global__ void k_poolout(float* __restrict__ out) {
    int idx = blockIdx.x * blockDim.x + threadIdx.x;
    if (idx >= cG * 128) return;
    int b = idx >> 7;
    out[idx] = g_pool[idx] / fmaxf(g_cnt[b], 1.f);
}

// ---------------------------------------------------------------------------
// Launch
// ---------------------------------------------------------------------------
extern "C" void kernel_launch(void* const* d_in, const int* in_sizes, int n_in,
                              void* d_out, int out_size) {
    const float* x   = (const float*)d_in[0];
    const int*   ei  = (const int*)d_in[1];
    const int*   bat = (const int*)d_in[2];
    const float* Wp  = (const float*)d_in[3];
    const float* bp  = (const float*)d_in[4];
    const float* Wq  = (const float*)d_in[5];
    const float* bq  = (const float*)d_in[6];
    const float* Wk  = (const float*)d_in[7];
    const float* bk  = (const float*)d_in[8];
    const float* Wv  = (const float*)d_in[9];
    const float* bv  = (const float*)d_in[10];
    const float* Ws  = (const float*)d_in[11];
    const float* bs  = (const float*)d_in[12];
    const float* Wb  = (const float*)d_in[13];
    const float* Wq3 = (const float*)d_in[14];
    const float* bq3 = (const float*)d_in[15];
    const float* Wk3 = (const float*)d_in[16];
    const float* bk3 = (const float*)d_in[17];
    const float* Wv3 = (const float*)d_in[18];
    const float* bv3 = (const float*)d_in[19];
    const float* Ws3 = (const float*)d_in[20];
    const float* bs3 = (const float*)d_in[21];
    const float* Wb3 = (const float*)d_in[22];
    const float* bng = (const float*)d_in[23];
    const float* bnb = (const float*)d_in[24];
    float* out = (float*)d_out;
    const int* src = ei;
    const int* dst = ei + cE;

    float *p_h, *p_q, *p_k, *p_v, *p_r;
    cudaGetSymbolAddress((void**)&p_h, g_h);
    cudaGetSymbolAddress((void**)&p_q, g_q);
    cudaGetSymbolAddress((void**)&p_k, g_k);
    cudaGetSymbolAddress((void**)&p_v, g_v);
    cudaGetSymbolAddress((void**)&p_r, g_r);

    const int nodeWarps = (cN + 7) / 8;       // 8 warps / 256-thread block
    const int elemBlks  = (cN * 128 + 255) / 256;
    dim3 g128((cN + 63) / 64, 2);
    dim3 g1024((cN + 63) / 64, 16);

    // CSR build (graph fixed, rebuilt each launch for determinism-of-work)
    k_degzero<<<(cN + 255) / 256, 256>>>();
    k_deg<<<(cE + 255) / 256, 256>>>(dst);
    k_scan<<<1, 1024>>>();
    k_scatter<<<(cE + 255) / 256, 256>>>(src, dst);

    // initial projection
    k_gemm<<<g128, 256>>>(x, Wp, bp, p_h, 128);

    // layers 0..2 (heads=8, d=16, concat)
    for (int i = 0; i < 3; i++) {
        k_gemm<<<g128, 256>>>(p_h, Wq + i * 16384, bq + i * 128, p_q, 128);
        k_gemm<<<g128, 256>>>(p_h, Wk + i * 16384, bk + i * 128, p_k, 128);
        k_gemm<<<g128, 256>>>(p_h, Wv + i * 16384, bv + i * 128, p_v, 128);
        k_gemm<<<g128, 256>>>(p_h, Ws + i * 16384, bs + i * 128, p_r, 128);
        k_logits<<<(cE * 8 + 255) / 256, 256>>>(src, dst, 16, 0.25f);
        k_attn16<<<nodeWarps, 256>>>();
        k_beta<<<nodeWarps, 256>>>(Wb + i * 384);
        k_bnzero<<<1, 128>>>();
        k_bnstat<<<256, 128>>>();
        k_bnapply<<<elemBlks, 256>>>(bng + i * 128, bnb + i * 128);
    }

    // layer 3 (heads=8, d=128, head-mean)
    k_gemm<<<g1024, 256>>>(p_h, Wq3, bq3, p_q, 1024);
    k_gemm<<<g1024, 256>>>(p_h, Wk3, bk3, p_k, 1024);
    k_gemm<<<g1024, 256>>>(p_h, Wv3, bv3, p_v, 1024);
    k_gemm<<<g128, 256>>>(p_h, Ws3, bs3, p_r, 128);
    k_logits<<<(cE * 8 + 255) / 256, 256>>>(src, dst, 128, 0.08838834764831845f);
    k_attn128<<<(cN * 8 + 7) / 8, 256>>>();
    k_beta3<<<nodeWarps, 256>>>(Wb3);
    k_bnzero<<<1, 128>>>();
    k_bnstat<<<256, 128>>>();
    k_bnapply<<<elemBlks, 256>>>(bng + 3 * 128, bnb + 3 * 128);

    // global mean pool
    k_poolzero<<<32, 256>>>();
    k_pool<<<elemBlks, 256>>>(bat);
    k_poolout<<<32, 256>>>(out);
}

// round 15
// speedup vs baseline: 2.1949x; 2.0999x over previous
#include <cuda_runtime.h>
#include <cuda_bf16.h>
#include <cstdint>
#include <math.h>

// Problem constants
static constexpr int cN = 20000;   // nodes
static constexpr int cE = 160000;  // edges
static constexpr int cG = 64;      // graphs

// ---------------------------------------------------------------------------
// Scratch (device globals: allocation-free rule)
// ---------------------------------------------------------------------------
__device__ float g_h[cN * 128];
__device__ float g_q[cN * 1024];
__device__ float g_k[cN * 1024];
__device__ float g_v[cN * 1024];
__device__ float g_r[cN * 128];
__device__ float g_out[cN * 1024];
__device__ float g_logits[cE * 8];
__device__ int   g_deg[cN];
__device__ int   g_rowptr[cN + 1];
__device__ int   g_cursor[cN];
__device__ int   g_perm[cE];
__device__ int   g_srcp[cE];
__device__ float g_bnsum[128];
__device__ float g_bnsq[128];
__device__ float g_pool[cG * 128];
__device__ float g_cnt[cG];

// ---------------------------------------------------------------------------
// CSR build
// ---------------------------------------------------------------------------
__global__ void k_degzero() {
    int i = blockIdx.x * blockDim.x + threadIdx.x;
    if (i < cN) g_deg[i] = 0;
}

__global__ void k_deg(const int* __restrict__ dst) {
    int e = blockIdx.x * blockDim.x + threadIdx.x;
    if (e < cE) atomicAdd(&g_deg[dst[e]], 1);
}

// single-block exclusive scan over g_deg -> g_rowptr, g_cursor
__global__ void k_scan() {
    __shared__ int warpsum[32];
    __shared__ int s_carry;
    int tid = threadIdx.x;              // 1024 threads
    int lane = tid & 31, w = tid >> 5;
    if (tid == 0) s_carry = 0;
    __syncthreads();
    for (int base = 0; base < cN; base += 1024) {
        int i = base + tid;
        int v = (i < cN) ? g_deg[i] : 0;
        int x = v;
        #pragma unroll
        for (int o = 1; o < 32; o <<= 1) {
            int y = __shfl_up_sync(0xffffffffu, x, o);
            if (lane >= o) x += y;
        }
        if (lane == 31) warpsum[w] = x;
        __syncthreads();
        if (w == 0) {
            int y = warpsum[lane];
            #pragma unroll
            for (int o = 1; o < 32; o <<= 1) {
                int z = __shfl_up_sync(0xffffffffu, y, o);
                if (lane >= o) y += z;
            }
            warpsum[lane] = y;
        }
        __syncthreads();
        int incl = x + (w > 0 ? warpsum[w - 1] : 0) + s_carry;
        int excl = incl - v;
        if (i < cN) { g_rowptr[i] = excl; g_cursor[i] = excl; }
        if (i == cN - 1) g_rowptr[cN] = incl;
        __syncthreads();
        if (tid == 1023) s_carry = incl;
        __syncthreads();
    }
}

__global__ void k_scatter(const int* __restrict__ src, const int* __restrict__ dst) {
    int e = blockIdx.x * blockDim.x + threadIdx.x;
    if (e < cE) {
        int d = dst[e];
        int pos = atomicAdd(&g_cursor[d], 1);
        g_perm[pos] = e;
        g_srcp[pos] = src[e];
    }
}

// ---------------------------------------------------------------------------
// TF32 tensor-core GEMM:  C[cN, M] = A[cN, 128] @ W[128, M] + bias
// BM=128 BN=64 BK=32, 256 threads, 8 warps (4 x 2), warp tile 32x32
// mma.sync.aligned.m16n8k8.row.col.f32.tf32.tf32.f32
// ---------------------------------------------------------------------------
__device__ __forceinline__ float to_tf32(float x) {
    uint32_t u;
    asm("cvt.rna.tf32.f32 %0, %1;" : "=r"(u) : "f"(x));
    return __uint_as_float(u);
}

__global__ __launch_bounds__(256) void k_gemm_tf32(
        const float* __restrict__ A, const float* __restrict__ W,
        const float* __restrict__ bias, float* __restrict__ C, int M) {
    // padded rows: A stride 36 floats, B stride 72 floats (conflict-free LDS)
    __shared__ float As[128][36];
    __shared__ float Bs[32][72];

    const int bm = blockIdx.x * 128, bn = blockIdx.y * 64;
    const int tid = threadIdx.x;
    const int lane = tid & 31, w = tid >> 5;
    const int wm = (w & 3) * 32;     // warp row offset in block tile
    const int wn = (w >> 2) * 32;    // warp col offset in block tile
    const int g = lane >> 2, tg = lane & 3;

    float acc[2][4][4];
    #pragma unroll
    for (int mt = 0; mt < 2; mt++)
        #pragma unroll
        for (int nt = 0; nt < 4; nt++)
            #pragma unroll
            for (int i = 0; i < 4; i++) acc[mt][nt][i] = 0.f;

    for (int k0 = 0; k0 < 128; k0 += 32) {
        // --- load A tile: 128 x 32 floats = 1024 float4, 4 per thread ---
        #pragma unroll
        for (int i = 0; i < 4; i++) {
            int id = tid + i * 256;
            int r = id >> 3, c4 = (id & 7) * 4;
            int row = bm + r;
            float4 val = make_float4(0.f, 0.f, 0.f, 0.f);
            if (row < cN) val = *(const float4*)&A[(size_t)row * 128 + k0 + c4];
            val.x = to_tf32(val.x); val.y = to_tf32(val.y);
            val.z = to_tf32(val.z); val.w = to_tf32(val.w);
            *(float4*)&As[r][c4] = val;
        }
        // --- load B tile: 32 x 64 floats = 512 float4, 2 per thread ---
        #pragma unroll
        for (int i = 0; i < 2; i++) {
            int id = tid + i * 256;
            int r = id >> 4, c4 = (id & 15) * 4;
            float4 val = *(const float4*)&W[(size_t)(k0 + r) * M + bn + c4];
            val.x = to_tf32(val.x); val.y = to_tf32(val.y);
            val.z = to_tf32(val.z); val.w = to_tf32(val.w);
            *(float4*)&Bs[r][c4] = val;
        }
        __syncthreads();

        #pragma unroll
        for (int kk = 0; kk < 32; kk += 8) {
            uint32_t a[2][4], b[4][2];
            #pragma unroll
            for (int mt = 0; mt < 2; mt++) {
                int r0 = wm + mt * 16;
                a[mt][0] = __float_as_uint(As[r0 + g][kk + tg]);
                a[mt][1] = __float_as_uint(As[r0 + g + 8][kk + tg]);
                a[mt][2] = __float_as_uint(As[r0 + g][kk + tg + 4]);
                a[mt][3] = __float_as_uint(As[r0 + g + 8][kk + tg + 4]);
            }
            #pragma unroll
            for (int nt = 0; nt < 4; nt++) {
                int c0 = wn + nt * 8 + g;
                b[nt][0] = __float_as_uint(Bs[kk + tg][c0]);
                b[nt][1] = __float_as_uint(Bs[kk + tg + 4][c0]);
            }
            #pragma unroll
            for (int mt = 0; mt < 2; mt++)
                #pragma unroll
                for (int nt = 0; nt < 4; nt++) {
                    asm volatile(
                        "mma.sync.aligned.m16n8k8.row.col.f32.tf32.tf32.f32 "
                        "{%0,%1,%2,%3}, {%4,%5,%6,%7}, {%8,%9}, {%0,%1,%2,%3};\n"
                        : "+f"(acc[mt][nt][0]), "+f"(acc[mt][nt][1]),
                          "+f"(acc[mt][nt][2]), "+f"(acc[mt][nt][3])
                        : "r"(a[mt][0]), "r"(a[mt][1]), "r"(a[mt][2]), "r"(a[mt][3]),
                          "r"(b[nt][0]), "r"(b[nt][1]));
                }
        }
        __syncthreads();
    }

    // --- epilogue: bias + store ---
    #pragma unroll
    for (int mt = 0; mt < 2; mt++) {
        #pragma unroll
        for (int nt = 0; nt < 4; nt++) {
            int col = bn + wn + nt * 8 + tg * 2;
            float bx = bias[col], by = bias[col + 1];
            int row0 = bm + wm + mt * 16 + g;
            if (row0 < cN) {
                float2 v = {acc[mt][nt][0] + bx, acc[mt][nt][1] + by};
                *(float2*)&C[(size_t)row0 * M + col] = v;
            }
            if (row0 + 8 < cN) {
                float2 v = {acc[mt][nt][2] + bx, acc[mt][nt][3] + by};
                *(float2*)&C[(size_t)(row0 + 8) * M + col] = v;
            }
        }
    }
}

// ---------------------------------------------------------------------------
// Edge attention logits: logits[e,h] = dot(q[dst,h,:], k[src,h,:]) * scale
// ---------------------------------------------------------------------------
__global__ void k_logits(const int* __restrict__ src, const int* __restrict__ dst,
                         int d, float scale) {
    int idx = blockIdx.x * blockDim.x + threadIdx.x;
    if (idx >= cE * 8) return;
    int e = idx >> 3, h = idx & 7;
    int s = src[e], t = dst[e];
    const float4* qp = (const float4*)(g_q + (size_t)t * (8 * d) + h * d);
    const float4* kp = (const float4*)(g_k + (size_t)s * (8 * d) + h * d);
    float a0 = 0.f, a1 = 0.f;
    int n4 = d >> 2;
    #pragma unroll 4
    for (int j = 0; j < n4; j += 2) {
        float4 a = qp[j],     b = kp[j];
        float4 c = qp[j + 1], dd = kp[j + 1];
        a0 += a.x * b.x + a.y * b.y + a.z * b.z + a.w * b.w;
        a1 += c.x * dd.x + c.y * dd.y + c.z * dd.z + c.w * dd.w;
    }
    g_logits[idx] = (a0 + a1) * scale;
}

// ---------------------------------------------------------------------------
// Segment softmax + aggregation, d=16 (layers 0..2): one warp per node.
// ---------------------------------------------------------------------------
__global__ void k_attn16() {
    int n = blockIdx.x * 8 + (threadIdx.x >> 5);
    if (n >= cN) return;
    int lane = threadIdx.x & 31;
    int beg = g_rowptr[n], end = g_rowptr[n + 1];
    int h = lane & 7;
    float mx = -1e30f;
    for (int i = beg + (lane >> 3); i < end; i += 4)
        mx = fmaxf(mx, g_logits[g_perm[i] * 8 + h]);
    mx = fmaxf(mx, __shfl_xor_sync(0xffffffffu, mx, 8));
    mx = fmaxf(mx, __shfl_xor_sync(0xffffffffu, mx, 16));
    float den = 0.f;
    for (int i = beg + (lane >> 3); i < end; i += 4)
        den += __expf(g_logits[g_perm[i] * 8 + h] - mx);
    den += __shfl_xor_sync(0xffffffffu, den, 8);
    den += __shfl_xor_sync(0xffffffffu, den, 16);
    int hh = lane >> 2;
    float m2 = __shfl_sync(0xffffffffu, mx, hh);
    float d2 = __shfl_sync(0xffffffffu, den, hh);
    float rden = 1.f / (d2 + 1e-16f);
    float4 acc = {0.f, 0.f, 0.f, 0.f};
    for (int i = beg; i < end; i++) {
        float w = __expf(g_logits[g_perm[i] * 8 + hh] - m2) * rden;
        const float4 vv = *(const float4*)(g_v + (size_t)g_srcp[i] * 128 + lane * 4);
        acc.x += w * vv.x; acc.y += w * vv.y; acc.z += w * vv.z; acc.w += w * vv.w;
    }
    *(float4*)(g_out + (size_t)n * 128 + lane * 4) = acc;
}

// d=128 (layer 3): one warp per (node, head)
__global__ void k_attn128() {
    int wid = blockIdx.x * 8 + (threadIdx.x >> 5);
    if (wid >= cN * 8) return;
    int n = wid >> 3, h = wid & 7;
    int lane = threadIdx.x & 31;
    int beg = g_rowptr[n], end = g_rowptr[n + 1];
    float mx = -1e30f;
    for (int i = beg + lane; i < end; i += 32)
        mx = fmaxf(mx, g_logits[g_perm[i] * 8 + h]);
    #pragma unroll
    for (int o = 16; o; o >>= 1) mx = fmaxf(mx, __shfl_xor_sync(0xffffffffu, mx, o));
    float den = 0.f;
    for (int i = beg + lane; i < end; i += 32)
        den += __expf(g_logits[g_perm[i] * 8 + h] - mx);
    #pragma unroll
    for (int o = 16; o; o >>= 1) den += __shfl_xor_sync(0xffffffffu, den, o);
    float rden = 1.f / (den + 1e-16f);
    float4 acc = {0.f, 0.f, 0.f, 0.f};
    for (int i = beg; i < end; i++) {
        float w = __expf(g_logits[g_perm[i] * 8 + h] - mx) * rden;
        const float4 vv = *(const float4*)(g_v + (size_t)g_srcp[i] * 1024 + h * 128 + lane * 4);
        acc.x += w * vv.x; acc.y += w * vv.y; acc.z += w * vv.z; acc.w += w * vv.w;
    }
    *(float4*)(g_out + (size_t)n * 1024 + h * 128 + lane * 4) = acc;
}

// ---------------------------------------------------------------------------
// Beta-gated skip
// ---------------------------------------------------------------------------
__device__ __forceinline__ void beta_core(int n, int lane, float4 o, const float* Wb) {
    float4 r  = *(const float4*)&g_r[(size_t)n * 128 + lane * 4];
    float4 w0 = *(const float4*)&Wb[lane * 4];
    float4 w1 = *(const float4*)&Wb[128 + lane * 4];
    float4 w2 = *(const float4*)&Wb[256 + lane * 4];
    float s = o.x * (w0.x + w2.x) + r.x * (w1.x - w2.x)
            + o.y * (w0.y + w2.y) + r.y * (w1.y - w2.y)
            + o.z * (w0.z + w2.z) + r.z * (w1.z - w2.z)
            + o.w * (w0.w + w2.w) + r.w * (w1.w - w2.w);
    #pragma unroll
    for (int off = 16; off; off >>= 1) s += __shfl_xor_sync(0xffffffffu, s, off);
    float g = 1.f / (1.f + __expf(-s));
    float4 res;
    res.x = g * r.x + (1.f - g) * o.x;
    res.y = g * r.y + (1.f - g) * o.y;
    res.z = g * r.z + (1.f - g) * o.z;
    res.w = g * r.w + (1.f - g) * o.w;
    *(float4*)&g_h[(size_t)n * 128 + lane * 4] = res;
}

__global__ void k_beta(const float* __restrict__ Wb) {
    int n = blockIdx.x * 8 + (threadIdx.x >> 5);
    if (n >= cN) return;
    int lane = threadIdx.x & 31;
    float4 o = *(const float4*)&g_out[(size_t)n * 128 + lane * 4];
    beta_core(n, lane, o, Wb);
}

__global__ void k_beta3(const float* __restrict__ Wb) {
    int n = blockIdx.x * 8 + (threadIdx.x >> 5);
    if (n >= cN) return;
    int lane = threadIdx.x & 31;
    float4 o = {0.f, 0.f, 0.f, 0.f};
    #pragma unroll
    for (int hh = 0; hh < 8; hh++) {
        float4 t = *(const float4*)&g_out[(size_t)n * 1024 + hh * 128 + lane * 4];
        o.x += t.x; o.y += t.y; o.z += t.z; o.w += t.w;
    }
    o.x *= 0.125f; o.y *= 0.125f; o.z *= 0.125f; o.w *= 0.125f;
    beta_core(n, lane, o, Wb);
}

// ---------------------------------------------------------------------------
// BatchNorm over nodes (per column), fused ReLU in apply
// ---------------------------------------------------------------------------
__global__ void k_bnzero() {
    int i = threadIdx.x;
    if (i < 128) { g_bnsum[i] = 0.f; g_bnsq[i] = 0.f; }
}

__global__ void k_bnstat() {
    int c = threadIdx.x;  // 128 threads
    float s = 0.f, sq = 0.f;
    for (int row = blockIdx.x; row < cN; row += gridDim.x) {
        float x = g_h[(size_t)row * 128 + c];
        s += x; sq += x * x;
    }
    atomicAdd(&g_bnsum[c], s);
    atomicAdd(&g_bnsq[c], sq);
}

__global__ void k_bnapply(const float* __restrict__ gamma, const float* __restrict__ beta) {
    int idx = blockIdx.x * blockDim.x + threadIdx.x;
    if (idx >= cN * 128) return;
    int c = idx & 127;
    float mu = g_bnsum[c] * (1.f / cN);
    float var = g_bnsq[c] * (1.f / cN) - mu * mu;
    float x = (g_h[idx] - mu) * rsqrtf(var + 1e-5f) * gamma[c] + beta[c];
    g_h[idx] = fmaxf(x, 0.f);
}

// ---------------------------------------------------------------------------
// Global mean pool per graph
// ---------------------------------------------------------------------------
__global__ void k_poolzero() {
    int i = blockIdx.x * blockDim.x + threadIdx.x;
    if (i < cG * 128) g_pool[i] = 0.f;
    if (i < cG) g_cnt[i] = 0.f;
}

__global__ void k_pool(const int* __restrict__ batch) {
    int idx = blockIdx.x * blockDim.x + threadIdx.x;
    if (idx >= cN * 128) return;
    int n = idx >> 7, c = idx & 127;
    int b = batch[n];
    atomicAdd(&g_pool[b * 128 + c], g_h[idx]);
    if (c == 0) atomicAdd(&g_cnt[b], 1.f);
}

__global__ void k_poolout(float* __restrict__ out) {
    int idx = blockIdx.x * blockDim.x + threadIdx.x;
    if (idx >= cG * 128) return;
    int b = idx >> 7;
    out[idx] = g_pool[idx] / fmaxf(g_cnt[b], 1.f);
}

// ---------------------------------------------------------------------------
// Launch
// ---------------------------------------------------------------------------
extern "C" void kernel_launch(void* const* d_in, const int* in_sizes, int n_in,
                              void* d_out, int out_size) {
    const float* x   = (const float*)d_in[0];
    const int*   ei  = (const int*)d_in[1];
    const int*   bat = (const int*)d_in[2];
    const float* Wp  = (const float*)d_in[3];
    const float* bp  = (const float*)d_in[4];
    const float* Wq  = (const float*)d_in[5];
    const float* bq  = (const float*)d_in[6];
    const float* Wk  = (const float*)d_in[7];
    const float* bk  = (const float*)d_in[8];
    const float* Wv  = (const float*)d_in[9];
    const float* bv  = (const float*)d_in[10];
    const float* Ws  = (const float*)d_in[11];
    const float* bs  = (const float*)d_in[12];
    const float* Wb  = (const float*)d_in[13];
    const float* Wq3 = (const float*)d_in[14];
    const float* bq3 = (const float*)d_in[15];
    const float* Wk3 = (const float*)d_in[16];
    const float* bk3 = (const float*)d_in[17];
    const float* Wv3 = (const float*)d_in[18];
    const float* bv3 = (const float*)d_in[19];
    const float* Ws3 = (const float*)d_in[20];
    const float* bs3 = (const float*)d_in[21];
    const float* Wb3 = (const float*)d_in[22];
    const float* bng = (const float*)d_in[23];
    const float* bnb = (const float*)d_in[24];
    float* out = (float*)d_out;
    const int* src = ei;
    const int* dst = ei + cE;

    float *p_h, *p_q, *p_k, *p_v, *p_r;
    cudaGetSymbolAddress((void**)&p_h, g_h);
    cudaGetSymbolAddress((void**)&p_q, g_q);
    cudaGetSymbolAddress((void**)&p_k, g_k);
    cudaGetSymbolAddress((void**)&p_v, g_v);
    cudaGetSymbolAddress((void**)&p_r, g_r);

    const int nodeWarps = (cN + 7) / 8;       // 8 warps / 256-thread block
    const int elemBlks  = (cN * 128 + 255) / 256;
    dim3 g128((cN + 127) / 128, 2);           // BM=128, BN=64
    dim3 g1024((cN + 127) / 128, 16);

    // CSR build
    k_degzero<<<(cN + 255) / 256, 256>>>();
    k_deg<<<(cE + 255) / 256, 256>>>(dst);
    k_scan<<<1, 1024>>>();
    k_scatter<<<(cE + 255) / 256, 256>>>(src, dst);

    // initial projection
    k_gemm_tf32<<<g128, 256>>>(x, Wp, bp, p_h, 128);

    // layers 0..2 (heads=8, d=16, concat)
    for (int i = 0; i < 3; i++) {
        k_gemm_tf32<<<g128, 256>>>(p_h, Wq + i * 16384, bq + i * 128, p_q, 128);
        k_gemm_tf32<<<g128, 256>>>(p_h, Wk + i * 16384, bk + i * 128, p_k, 128);
        k_gemm_tf32<<<g128, 256>>>(p_h, Wv + i * 16384, bv + i * 128, p_v, 128);
        k_gemm_tf32<<<g128, 256>>>(p_h, Ws + i * 16384, bs + i * 128, p_r, 128);
        k_logits<<<(cE * 8 + 255) / 256, 256>>>(src, dst, 16, 0.25f);
        k_attn16<<<nodeWarps, 256>>>();
        k_beta<<<nodeWarps, 256>>>(Wb + i * 384);
        k_bnzero<<<1, 128>>>();
        k_bnstat<<<256, 128>>>();
        k_bnapply<<<elemBlks, 256>>>(bng + i * 128, bnb + i * 128);
    }

    // layer 3 (heads=8, d=128, head-mean)
    k_gemm_tf32<<<g1024, 256>>>(p_h, Wq3, bq3, p_q, 1024);
    k_gemm_tf32<<<g1024, 256>>>(p_h, Wk3, bk3, p_k, 1024);
    k_gemm_tf32<<<g1024, 256>>>(p_h, Wv3, bv3, p_v, 1024);
    k_gemm_tf32<<<g128, 256>>>(p_h, Ws3, bs3, p_r, 128);
    k_logits<<<(cE * 8 + 255) / 256, 256>>>(src, dst, 128, 0.08838834764831845f);
    k_attn128<<<(cN * 8 + 7) / 8, 256>>>();
    k_beta3<<<nodeWarps, 256>>>(Wb3);
    k_bnzero<<<1, 128>>>();
    k_bnstat<<<256, 128>>>();
    k_bnapply<<<elemBlks, 256>>>(bng + 3 * 128, bnb + 3 * 128);

    // global mean pool
    k_poolzero<<<32, 256>>>();
    k_pool<<<elemBlks, 256>>>(bat);
    k_poolout<<<32, 256>>>(out);
}

// round 16
// speedup vs baseline: 2.8695x; 1.3073x over previous
#include <cuda_runtime.h>
#include <cuda_bf16.h>
#include <cstdint>
#include <math.h>

// Problem constants
static constexpr int cN = 20000;   // nodes
static constexpr int cE = 160000;  // edges
static constexpr int cG = 64;      // graphs

// ---------------------------------------------------------------------------
// Scratch (device globals: allocation-free rule)
// ---------------------------------------------------------------------------
__device__ float g_h[cN * 128];
__device__ float g_q[cN * 1024];
__device__ float g_k[cN * 1024];
__device__ float g_v[cN * 1024];
__device__ float g_r[cN * 128];
__device__ float g_out[cN * 1024];
__device__ int   g_deg[cN];
__device__ int   g_rowptr[cN + 1];
__device__ int   g_cursor[cN];
__device__ int   g_srcp[cE];
__device__ float g_bnsum[128];
__device__ float g_bnsq[128];
__device__ float g_pool[cG * 128];
__device__ float g_cnt[cG];

// ---------------------------------------------------------------------------
// CSR build
// ---------------------------------------------------------------------------
__global__ void k_degzero() {
    int i = blockIdx.x * blockDim.x + threadIdx.x;
    if (i < cN) g_deg[i] = 0;
}

__global__ void k_deg(const int* __restrict__ dst) {
    int e = blockIdx.x * blockDim.x + threadIdx.x;
    if (e < cE) atomicAdd(&g_deg[dst[e]], 1);
}

// single-block exclusive scan over g_deg -> g_rowptr, g_cursor
__global__ void k_scan() {
    __shared__ int warpsum[32];
    __shared__ int s_carry;
    int tid = threadIdx.x;              // 1024 threads
    int lane = tid & 31, w = tid >> 5;
    if (tid == 0) s_carry = 0;
    __syncthreads();
    for (int base = 0; base < cN; base += 1024) {
        int i = base + tid;
        int v = (i < cN) ? g_deg[i] : 0;
        int x = v;
        #pragma unroll
        for (int o = 1; o < 32; o <<= 1) {
            int y = __shfl_up_sync(0xffffffffu, x, o);
            if (lane >= o) x += y;
        }
        if (lane == 31) warpsum[w] = x;
        __syncthreads();
        if (w == 0) {
            int y = warpsum[lane];
            #pragma unroll
            for (int o = 1; o < 32; o <<= 1) {
                int z = __shfl_up_sync(0xffffffffu, y, o);
                if (lane >= o) y += z;
            }
            warpsum[lane] = y;
        }
        __syncthreads();
        int incl = x + (w > 0 ? warpsum[w - 1] : 0) + s_carry;
        int excl = incl - v;
        if (i < cN) { g_rowptr[i] = excl; g_cursor[i] = excl; }
        if (i == cN - 1) g_rowptr[cN] = incl;
        __syncthreads();
        if (tid == 1023) s_carry = incl;
        __syncthreads();
    }
}

__global__ void k_scatter(const int* __restrict__ src, const int* __restrict__ dst) {
    int e = blockIdx.x * blockDim.x + threadIdx.x;
    if (e < cE) {
        int d = dst[e];
        int pos = atomicAdd(&g_cursor[d], 1);
        g_srcp[pos] = src[e];
    }
}

// ---------------------------------------------------------------------------
// TF32 tensor-core GEMM:  C[cN, M] = A[cN, 128] @ W[128, M] + bias
// BM=128 BN=64 BK=32, 256 threads, 8 warps (4 x 2), warp tile 32x32
// ---------------------------------------------------------------------------
__device__ __forceinline__ float to_tf32(float x) {
    uint32_t u;
    asm("cvt.rna.tf32.f32 %0, %1;" : "=r"(u) : "f"(x));
    return __uint_as_float(u);
}

__global__ __launch_bounds__(256) void k_gemm_tf32(
        const float* __restrict__ A, const float* __restrict__ W,
        const float* __restrict__ bias, float* __restrict__ C, int M) {
    __shared__ float As[128][36];
    __shared__ float Bs[32][72];

    const int bm = blockIdx.x * 128, bn = blockIdx.y * 64;
    const int tid = threadIdx.x;
    const int lane = tid & 31, w = tid >> 5;
    const int wm = (w & 3) * 32;
    const int wn = (w >> 2) * 32;
    const int g = lane >> 2, tg = lane & 3;

    float acc[2][4][4];
    #pragma unroll
    for (int mt = 0; mt < 2; mt++)
        #pragma unroll
        for (int nt = 0; nt < 4; nt++)
            #pragma unroll
            for (int i = 0; i < 4; i++) acc[mt][nt][i] = 0.f;

    for (int k0 = 0; k0 < 128; k0 += 32) {
        #pragma unroll
        for (int i = 0; i < 4; i++) {
            int id = tid + i * 256;
            int r = id >> 3, c4 = (id & 7) * 4;
            int row = bm + r;
            float4 val = make_float4(0.f, 0.f, 0.f, 0.f);
            if (row < cN) val = *(const float4*)&A[(size_t)row * 128 + k0 + c4];
            val.x = to_tf32(val.x); val.y = to_tf32(val.y);
            val.z = to_tf32(val.z); val.w = to_tf32(val.w);
            *(float4*)&As[r][c4] = val;
        }
        #pragma unroll
        for (int i = 0; i < 2; i++) {
            int id = tid + i * 256;
            int r = id >> 4, c4 = (id & 15) * 4;
            float4 val = *(const float4*)&W[(size_t)(k0 + r) * M + bn + c4];
            val.x = to_tf32(val.x); val.y = to_tf32(val.y);
            val.z = to_tf32(val.z); val.w = to_tf32(val.w);
            *(float4*)&Bs[r][c4] = val;
        }
        __syncthreads();

        #pragma unroll
        for (int kk = 0; kk < 32; kk += 8) {
            uint32_t a[2][4], b[4][2];
            #pragma unroll
            for (int mt = 0; mt < 2; mt++) {
                int r0 = wm + mt * 16;
                a[mt][0] = __float_as_uint(As[r0 + g][kk + tg]);
                a[mt][1] = __float_as_uint(As[r0 + g + 8][kk + tg]);
                a[mt][2] = __float_as_uint(As[r0 + g][kk + tg + 4]);
                a[mt][3] = __float_as_uint(As[r0 + g + 8][kk + tg + 4]);
            }
            #pragma unroll
            for (int nt = 0; nt < 4; nt++) {
                int c0 = wn + nt * 8 + g;
                b[nt][0] = __float_as_uint(Bs[kk + tg][c0]);
                b[nt][1] = __float_as_uint(Bs[kk + tg + 4][c0]);
            }
            #pragma unroll
            for (int mt = 0; mt < 2; mt++)
                #pragma unroll
                for (int nt = 0; nt < 4; nt++) {
                    asm volatile(
                        "mma.sync.aligned.m16n8k8.row.col.f32.tf32.tf32.f32 "
                        "{%0,%1,%2,%3}, {%4,%5,%6,%7}, {%8,%9}, {%0,%1,%2,%3};\n"
                        : "+f"(acc[mt][nt][0]), "+f"(acc[mt][nt][1]),
                          "+f"(acc[mt][nt][2]), "+f"(acc[mt][nt][3])
                        : "r"(a[mt][0]), "r"(a[mt][1]), "r"(a[mt][2]), "r"(a[mt][3]),
                          "r"(b[nt][0]), "r"(b[nt][1]));
                }
        }
        __syncthreads();
    }

    #pragma unroll
    for (int mt = 0; mt < 2; mt++) {
        #pragma unroll
        for (int nt = 0; nt < 4; nt++) {
            int col = bn + wn + nt * 8 + tg * 2;
            float bx = bias[col], by = bias[col + 1];
            int row0 = bm + wm + mt * 16 + g;
            if (row0 < cN) {
                float2 v = {acc[mt][nt][0] + bx, acc[mt][nt][1] + by};
                *(float2*)&C[(size_t)row0 * M + col] = v;
            }
            if (row0 + 8 < cN) {
                float2 v = {acc[mt][nt][2] + bx, acc[mt][nt][3] + by};
                *(float2*)&C[(size_t)(row0 + 8) * M + col] = v;
            }
        }
    }
}

// ---------------------------------------------------------------------------
// Fused attention (flash-style online softmax), d=16 layers: one warp/node.
// Lane l holds components [4l,4l+4) of the 128-wide row; head = l>>2.
// Logit for the lane's head reduced over its 4-lane group (16 dims).
// ---------------------------------------------------------------------------
__global__ void k_fattn16(float scale) {
    int n = blockIdx.x * 8 + (threadIdx.x >> 5);
    if (n >= cN) return;
    int lane = threadIdx.x & 31;
    int beg = g_rowptr[n], end = g_rowptr[n + 1];
    const float4 q = *(const float4*)&g_q[(size_t)n * 128 + lane * 4];
    float m = -1e30f, l = 0.f;
    float4 acc = {0.f, 0.f, 0.f, 0.f};
    for (int i = beg; i < end; i++) {
        int s = g_srcp[i];
        const float4 k4 = *(const float4*)&g_k[(size_t)s * 128 + lane * 4];
        const float4 v4 = *(const float4*)&g_v[(size_t)s * 128 + lane * 4];
        float p = q.x * k4.x + q.y * k4.y + q.z * k4.z + q.w * k4.w;
        p += __shfl_xor_sync(0xffffffffu, p, 1);
        p += __shfl_xor_sync(0xffffffffu, p, 2);
        p *= scale;
        float mn = fmaxf(m, p);
        float corr = __expf(m - mn);
        float wgt = __expf(p - mn);
        l = l * corr + wgt;
        acc.x = acc.x * corr + wgt * v4.x;
        acc.y = acc.y * corr + wgt * v4.y;
        acc.z = acc.z * corr + wgt * v4.z;
        acc.w = acc.w * corr + wgt * v4.w;
        m = mn;
    }
    float rl = 1.f / (l + 1e-16f);
    float4 o = {acc.x * rl, acc.y * rl, acc.z * rl, acc.w * rl};
    *(float4*)&g_out[(size_t)n * 128 + lane * 4] = o;
}

// d=128 (layer 3): one warp per (node, head), online softmax, full-warp dot.
__global__ void k_fattn128(float scale) {
    int wid = blockIdx.x * 8 + (threadIdx.x >> 5);
    if (wid >= cN * 8) return;
    int n = wid >> 3, h = wid & 7;
    int lane = threadIdx.x & 31;
    int beg = g_rowptr[n], end = g_rowptr[n + 1];
    const float4 q = *(const float4*)&g_q[(size_t)n * 1024 + h * 128 + lane * 4];
    float m = -1e30f, l = 0.f;
    float4 acc = {0.f, 0.f, 0.f, 0.f};
    for (int i = beg; i < end; i++) {
        int s = g_srcp[i];
        const float4 k4 = *(const float4*)&g_k[(size_t)s * 1024 + h * 128 + lane * 4];
        const float4 v4 = *(const float4*)&g_v[(size_t)s * 1024 + h * 128 + lane * 4];
        float p = q.x * k4.x + q.y * k4.y + q.z * k4.z + q.w * k4.w;
        #pragma unroll
        for (int o = 16; o; o >>= 1) p += __shfl_xor_sync(0xffffffffu, p, o);
        p *= scale;
        float mn = fmaxf(m, p);
        float corr = __expf(m - mn);
        float wgt = __expf(p - mn);
        l = l * corr + wgt;
        acc.x = acc.x * corr + wgt * v4.x;
        acc.y = acc.y * corr + wgt * v4.y;
        acc.z = acc.z * corr + wgt * v4.z;
        acc.w = acc.w * corr + wgt * v4.w;
        m = mn;
    }
    float rl = 1.f / (l + 1e-16f);
    float4 o = {acc.x * rl, acc.y * rl, acc.z * rl, acc.w * rl};
    *(float4*)&g_out[(size_t)n * 1024 + h * 128 + lane * 4] = o;
}

// ---------------------------------------------------------------------------
// Beta-gated skip
// ---------------------------------------------------------------------------
__device__ __forceinline__ void beta_core(int n, int lane, float4 o, const float* Wb) {
    float4 r  = *(const float4*)&g_r[(size_t)n * 128 + lane * 4];
    float4 w0 = *(const float4*)&Wb[lane * 4];
    float4 w1 = *(const float4*)&Wb[128 + lane * 4];
    float4 w2 = *(const float4*)&Wb[256 + lane * 4];
    float s = o.x * (w0.x + w2.x) + r.x * (w1.x - w2.x)
            + o.y * (w0.y + w2.y) + r.y * (w1.y - w2.y)
            + o.z * (w0.z + w2.z) + r.z * (w1.z - w2.z)
            + o.w * (w0.w + w2.w) + r.w * (w1.w - w2.w);
    #pragma unroll
    for (int off = 16; off; off >>= 1) s += __shfl_xor_sync(0xffffffffu, s, off);
    float g = 1.f / (1.f + __expf(-s));
    float4 res;
    res.x = g * r.x + (1.f - g) * o.x;
    res.y = g * r.y + (1.f - g) * o.y;
    res.z = g * r.z + (1.f - g) * o.z;
    res.w = g * r.w + (1.f - g) * o.w;
    *(float4*)&g_h[(size_t)n * 128 + lane * 4] = res;
}

__global__ void k_beta(const float* __restrict__ Wb) {
    int n = blockIdx.x * 8 + (threadIdx.x >> 5);
    if (n >= cN) return;
    int lane = threadIdx.x & 31;
    float4 o = *(const float4*)&g_out[(size_t)n * 128 + lane * 4];
    beta_core(n, lane, o, Wb);
}

__global__ void k_beta3(const float* __restrict__ Wb) {
    int n = blockIdx.x * 8 + (threadIdx.x >> 5);
    if (n >= cN) return;
    int lane = threadIdx.x & 31;
    float4 o = {0.f, 0.f, 0.f, 0.f};
    #pragma unroll
    for (int hh = 0; hh < 8; hh++) {
        float4 t = *(const float4*)&g_out[(size_t)n * 1024 + hh * 128 + lane * 4];
        o.x += t.x; o.y += t.y; o.z += t.z; o.w += t.w;
    }
    o.x *= 0.125f; o.y *= 0.125f; o.z *= 0.125f; o.w *= 0.125f;
    beta_core(n, lane, o, Wb);
}

// ---------------------------------------------------------------------------
// BatchNorm over nodes (per column), fused ReLU in apply
// ---------------------------------------------------------------------------
__global__ void k_bnzero() {
    int i = threadIdx.x;
    if (i < 128) { g_bnsum[i] = 0.f; g_bnsq[i] = 0.f; }
}

__global__ void k_bnstat() {
    int c = threadIdx.x;  // 128 threads
    float s = 0.f, sq = 0.f;
    for (int row = blockIdx.x; row < cN; row += gridDim.x) {
        float x = g_h[(size_t)row * 128 + c];
        s += x; sq += x * x;
    }
    atomicAdd(&g_bnsum[c], s);
    atomicAdd(&g_bnsq[c], sq);
}

__global__ void k_bnapply(const float* __restrict__ gamma, const float* __restrict__ beta) {
    int idx = blockIdx.x * blockDim.x + threadIdx.x;
    if (idx >= cN * 128) return;
    int c = idx & 127;
    float mu = g_bnsum[c] * (1.f / cN);
    float var = g_bnsq[c] * (1.f / cN) - mu * mu;
    float x = (g_h[idx] - mu) * rsqrtf(var + 1e-5f) * gamma[c] + beta[c];
    g_h[idx] = fmaxf(x, 0.f);
}

// ---------------------------------------------------------------------------
// Global mean pool per graph
// ---------------------------------------------------------------------------
__global__ void k_poolzero() {
    int i = blockIdx.x * blockDim.x + threadIdx.x;
    if (i < cG * 128) g_pool[i] = 0.f;
    if (i < cG) g_cnt[i] = 0.f;
}

__global__ void k_pool(const int* __restrict__ batch) {
    int idx = blockIdx.x * blockDim.x + threadIdx.x;
    if (idx >= cN * 128) return;
    int n = idx >> 7, c = idx & 127;
    int b = batch[n];
    atomicAdd(&g_pool[b * 128 + c], g_h[idx]);
    if (c == 0) atomicAdd(&g_cnt[b], 1.f);
}

__global__ void k_poolout(float* __restrict__ out) {
    int idx = blockIdx.x * blockDim.x + threadIdx.x;
    if (idx >= cG * 128) return;
    int b = idx >> 7;
    out[idx] = g_pool[idx] / fmaxf(g_cnt[b], 1.f);
}

// ---------------------------------------------------------------------------
// Launch
// ---------------------------------------------------------------------------
extern "C" void kernel_launch(void* const* d_in, const int* in_sizes, int n_in,
                              void* d_out, int out_size) {
    const float* x   = (const float*)d_in[0];
    const int*   ei  = (const int*)d_in[1];
    const int*   bat = (const int*)d_in[2];
    const float* Wp  = (const float*)d_in[3];
    const float* bp  = (const float*)d_in[4];
    const float* Wq  = (const float*)d_in[5];
    const float* bq  = (const float*)d_in[6];
    const float* Wk  = (const float*)d_in[7];
    const float* bk  = (const float*)d_in[8];
    const float* Wv  = (const float*)d_in[9];
    const float* bv  = (const float*)d_in[10];
    const float* Ws  = (const float*)d_in[11];
    const float* bs  = (const float*)d_in[12];
    const float* Wb  = (const float*)d_in[13];
    const float* Wq3 = (const float*)d_in[14];
    const float* bq3 = (const float*)d_in[15];
    const float* Wk3 = (const float*)d_in[16];
    const float* bk3 = (const float*)d_in[17];
    const float* Wv3 = (const float*)d_in[18];
    const float* bv3 = (const float*)d_in[19];
    const float* Ws3 = (const float*)d_in[20];
    const float* bs3 = (const float*)d_in[21];
    const float* Wb3 = (const float*)d_in[22];
    const float* bng = (const float*)d_in[23];
    const float* bnb = (const float*)d_in[24];
    float* out = (float*)d_out;
    const int* src = ei;
    const int* dst = ei + cE;

    float *p_h, *p_q, *p_k, *p_v, *p_r;
    cudaGetSymbolAddress((void**)&p_h, g_h);
    cudaGetSymbolAddress((void**)&p_q, g_q);
    cudaGetSymbolAddress((void**)&p_k, g_k);
    cudaGetSymbolAddress((void**)&p_v, g_v);
    cudaGetSymbolAddress((void**)&p_r, g_r);

    const int nodeWarps = (cN + 7) / 8;       // 8 warps / 256-thread block
    const int elemBlks  = (cN * 128 + 255) / 256;
    dim3 g128((cN + 127) / 128, 2);           // BM=128, BN=64
    dim3 g1024((cN + 127) / 128, 16);

    // CSR build
    k_degzero<<<(cN + 255) / 256, 256>>>();
    k_deg<<<(cE + 255) / 256, 256>>>(dst);
    k_scan<<<1, 1024>>>();
    k_scatter<<<(cE + 255) / 256, 256>>>(src, dst);

    // initial projection
    k_gemm_tf32<<<g128, 256>>>(x, Wp, bp, p_h, 128);

    // layers 0..2 (heads=8, d=16, concat)
    for (int i = 0; i < 3; i++) {
        k_gemm_tf32<<<g128, 256>>>(p_h, Wq + i * 16384, bq + i * 128, p_q, 128);
        k_gemm_tf32<<<g128, 256>>>(p_h, Wk + i * 16384, bk + i * 128, p_k, 128);
        k_gemm_tf32<<<g128, 256>>>(p_h, Wv + i * 16384, bv + i * 128, p_v, 128);
        k_gemm_tf32<<<g128, 256>>>(p_h, Ws + i * 16384, bs + i * 128, p_r, 128);
        k_fattn16<<<nodeWarps, 256>>>(0.25f);
        k_beta<<<nodeWarps, 256>>>(Wb + i * 384);
        k_bnzero<<<1, 128>>>();
        k_bnstat<<<256, 128>>>();
        k_bnapply<<<elemBlks, 256>>>(bng + i * 128, bnb + i * 128);
    }

    // layer 3 (heads=8, d=128, head-mean)
    k_gemm_tf32<<<g1024, 256>>>(p_h, Wq3, bq3, p_q, 1024);
    k_gemm_tf32<<<g1024, 256>>>(p_h, Wk3, bk3, p_k, 1024);
    k_gemm_tf32<<<g1024, 256>>>(p_h, Wv3, bv3, p_v, 1024);
    k_gemm_tf32<<<g128, 256>>>(p_h, Ws3, bs3, p_r, 128);
    k_fattn128<<<(cN * 8 + 7) / 8, 256>>>(0.08838834764831845f);
    k_beta3<<<nodeWarps, 256>>>(Wb3);
    k_bnzero<<<1, 128>>>();
    k_bnstat<<<256, 128>>>();
    k_bnapply<<<elemBlks, 256>>>(bng + 3 * 128, bnb + 3 * 128);

    // global mean pool
    k_poolzero<<<32, 256>>>();
    k_pool<<<elemBlks, 256>>>(bat);
    k_poolout<<<32, 256>>>(out);
}